// round 6
// baseline (speedup 1.0000x reference)
#include <cuda_runtime.h>
#include <cstdint>

// Problem constants (match reference_code)
#define IMG_W 3840
#define IMG_H 2160
#define NPIX (IMG_W * IMG_H)

#define SCALE_F 0.001f
#define D_CX 1919.5f
#define D_CY 1079.5f
#define D_FX 3000.0f
#define D_FY 3000.0f
#define R_CX 1919.5f
#define R_CY 1079.5f
#define R_FX 3050.0f
#define R_FY 3050.0f
#define FILL 10000.0f

// NPIX/16 float4-quads: each thread initializes 4 consecutive float4 (64 B)
#define NQUAD (NPIX / 16)

// ---------------------------------------------------------------------------
// Kernel 1: initialize output to FILL. 4x float4 per thread.
// ---------------------------------------------------------------------------
__global__ void init_fill_kernel(float4* __restrict__ out4) {
    int i = blockIdx.x * blockDim.x + threadIdx.x;
    if (i < NQUAD) {
        float4 f = make_float4(FILL, FILL, FILL, FILL);
        int b = i * 4;
        out4[b + 0] = f;
        out4[b + 1] = f;
        out4[b + 2] = f;
        out4[b + 3] = f;
    }
}

// ---------------------------------------------------------------------------
// Kernel 2: project + min-splat. 4 source pixels per thread (float4 load).
//
// Numerics: FROZEN from round 4 (bit-exact vs reference, rel_err = 0.0):
//   grid = (u-cx)*rn(1/fx)*SCALE   (XLA const-div->mul rewrite)
//   dot  = rounded mul + left-assoc rounded adds, no fma
//   proj = separate rn div/mul/add
//   trunc-toward-zero int casts
//
// px1/py1 derived by integer increment (exact equivalence):
//   for px >= 0.5: trunc(px+0.5) = trunc(px-0.5) + 1
//   for px in [0,0.5): trunc(px-0.5) = trunc(px+0.5) = 0
//
// Splat policy:
//   - in-bounds targets: unconditional atomicMin (REDG fire-and-forget)
//   - masked pixels (all targets collapse to (0,0)): __ldcg check-before-
//     atomic kills same-address serialization after warm-up
// ---------------------------------------------------------------------------
__global__ void splat_kernel(const float4* __restrict__ depth4,
                             const float* __restrict__ Rm,   // 9 floats
                             const float* __restrict__ Tv,   // 3 floats
                             int* __restrict__ outbits) {
    int i4 = blockIdx.x * blockDim.x + threadIdx.x;
    if (i4 >= NPIX / 4) return;

    const int W4 = IMG_W / 4;             // 960
    int v  = i4 / W4;
    int u0 = (i4 - v * W4) * 4;

    float4 dq = depth4[i4];
    float dvals[4] = {dq.x, dq.y, dq.z, dq.w};

    // Broadcast loads (uniform across warp)
    float r00 = Rm[0], r01 = Rm[1], r02 = Rm[2];
    float r10 = Rm[3], r11 = Rm[4], r12 = Rm[5];
    float r20 = Rm[6], r21 = Rm[7], r22 = Rm[8];
    float t0 = Tv[0], t1 = Tv[1], t2 = Tv[2];

    const float INV_DFX = 1.0f / D_FX;
    const float INV_DFY = 1.0f / D_FY;

    // gy depends only on v: hoist
    float gy = __fmul_rn(__fmul_rn(__fsub_rn((float)v, D_CY), INV_DFY), SCALE_F);

    #pragma unroll
    for (int j = 0; j < 4; j++) {
        int u = u0 + j;
        float dval = dvals[j];

        float gx = __fmul_rn(__fmul_rn(__fsub_rn((float)u, D_CX), INV_DFX), SCALE_F);
        float gz = SCALE_F;

        float p0 = __fmul_rn(dval, gx);
        float p1 = __fmul_rn(dval, gy);
        float p2 = __fmul_rn(dval, gz);

        // pts @ R : multiply-reduce, separate rn ops, left-assoc, NO fma.
        float x = __fadd_rn(__fadd_rn(__fmul_rn(p0, r00), __fmul_rn(p1, r10)),
                            __fmul_rn(p2, r20));
        float y = __fadd_rn(__fadd_rn(__fmul_rn(p0, r01), __fmul_rn(p1, r11)),
                            __fmul_rn(p2, r21));
        float d = __fadd_rn(__fadd_rn(__fmul_rn(p0, r02), __fmul_rn(p1, r12)),
                            __fmul_rn(p2, r22));

        x = __fadd_rn(x, t0);
        y = __fadd_rn(y, t1);
        d = __fadd_rn(d, t2);

        float dsafe = (d == 0.0f) ? 1.0f : d;
        float px = __fadd_rn(__fmul_rn(__fdiv_rn(x, dsafe), R_FX), R_CX);
        float py = __fadd_rn(__fmul_rn(__fdiv_rn(y, dsafe), R_FY), R_CY);
        if (d == 0.0f) { px = 0.0f; py = 0.0f; }

        bool mask = (px < 0.0f) | (px >= (float)IMG_W) |
                    (py < 0.0f) | (py >= (float)IMG_H);

        int vb = __float_as_int(dval);

        if (mask) {
            // all four targets collapse to (0,0): guarded single atomic
            if (__ldcg(&outbits[0]) > vb) atomicMin(&outbits[0], vb);
            continue;
        }

        // trunc-toward-zero casts; companions derived by integer increment
        int px0 = (int)__fsub_rn(px, 0.5f);
        int py0 = (int)__fsub_rn(py, 0.5f);
        bool xlo = (px < 0.5f);   // -> px1 == px0 == 0 (duplicate)
        bool ylo = (py < 0.5f);   // -> py1 == py0 == 0 (duplicate)
        int px1 = px0 + 1;
        int py1 = py0 + 1;

        // px1/py1 may hit W/H (dropped, as jax drops OOB scatter indices)
        bool x1ok = (!xlo) & (px1 < IMG_W);
        bool y1ok = (!ylo) & (py1 < IMG_H);

        int o00 = py0 * IMG_W + px0;
        atomicMin(&outbits[o00], vb);
        if (x1ok) atomicMin(&outbits[o00 + 1], vb);
        if (y1ok) {
            int o10 = o00 + IMG_W;
            atomicMin(&outbits[o10], vb);
            if (x1ok) atomicMin(&outbits[o10 + 1], vb);
        }
    }
}

// ---------------------------------------------------------------------------
// Kernel 3: FILL -> 0. 4x float4 per thread, L2-only loads.
// ---------------------------------------------------------------------------
__global__ void finalize_kernel(float4* __restrict__ out4) {
    int i = blockIdx.x * blockDim.x + threadIdx.x;
    if (i < NQUAD) {
        int b = i * 4;
        #pragma unroll
        for (int k = 0; k < 4; k++) {
            float4 q = __ldcg(&out4[b + k]);
            q.x = (q.x == FILL) ? 0.0f : q.x;
            q.y = (q.y == FILL) ? 0.0f : q.y;
            q.z = (q.z == FILL) ? 0.0f : q.z;
            q.w = (q.w == FILL) ? 0.0f : q.w;
            out4[b + k] = q;
        }
    }
}

extern "C" void kernel_launch(void* const* d_in, const int* in_sizes, int n_in,
                              void* d_out, int out_size) {
    const float* depth = (const float*)d_in[0];   // [H, W, 1] float32
    const float* Rm    = (const float*)d_in[1];   // [3, 3]
    const float* Tv    = (const float*)d_in[2];   // [3]
    float* out = (float*)d_out;                   // [H, W, 1] float32

    (void)in_sizes; (void)n_in; (void)out_size;

    int threads = 256;
    int blocksQ = (NQUAD + threads - 1) / threads;       // init/finalize
    int blocks4 = (NPIX / 4 + threads - 1) / threads;    // splat

    init_fill_kernel<<<blocksQ, threads>>>((float4*)out);
    splat_kernel<<<blocks4, threads>>>((const float4*)depth, Rm, Tv, (int*)out);
    finalize_kernel<<<blocksQ, threads>>>((float4*)out);
}

// round 7
// speedup vs baseline: 1.0500x; 1.0500x over previous
#include <cuda_runtime.h>
#include <cstdint>

// Problem constants (match reference_code)
#define IMG_W 3840
#define IMG_H 2160
#define NPIX (IMG_W * IMG_H)

#define SCALE_F 0.001f
#define D_CX 1919.5f
#define D_CY 1079.5f
#define D_FX 3000.0f
#define D_FY 3000.0f
#define R_CX 1919.5f
#define R_CY 1079.5f
#define R_FX 3050.0f
#define R_FY 3050.0f
#define FILL 10000.0f

// ---------------------------------------------------------------------------
// Kernel 1: initialize output to FILL (1x float4 per thread -- R5 shape)
// ---------------------------------------------------------------------------
__global__ void init_fill_kernel(float4* __restrict__ out4) {
    int i = blockIdx.x * blockDim.x + threadIdx.x;
    if (i < NPIX / 4) {
        out4[i] = make_float4(FILL, FILL, FILL, FILL);
    }
}

// ---------------------------------------------------------------------------
// Kernel 2: project + min-splat, 4 source pixels per thread.
//
// Numerics (px/py path): FROZEN from round 4, bit-exact vs reference.
//
// Cross-pixel merge: when the 4 pixels are all in-bounds, share py0 and
// y1ok, have no xlo, and px0 is exactly consecutive (+1 per pixel), their
// four 2x2 windows union to a 5-column strip; interior columns take the
// local min of the two contributing depths. atomicMin is associative, so
// this is semantically exact. 10 (or 5) atomics instead of 16.
// ---------------------------------------------------------------------------
__global__ void splat_kernel(const float4* __restrict__ depth4,
                             const float* __restrict__ Rm,   // 9 floats
                             const float* __restrict__ Tv,   // 3 floats
                             int* __restrict__ outbits) {
    int i4 = blockIdx.x * blockDim.x + threadIdx.x;
    if (i4 >= NPIX / 4) return;

    const int W4 = IMG_W / 4;             // 960
    int v  = i4 / W4;
    int u0 = (i4 - v * W4) * 4;

    float4 dq = depth4[i4];
    float dvals[4] = {dq.x, dq.y, dq.z, dq.w};

    // Broadcast loads (uniform across warp)
    float r00 = Rm[0], r01 = Rm[1], r02 = Rm[2];
    float r10 = Rm[3], r11 = Rm[4], r12 = Rm[5];
    float r20 = Rm[6], r21 = Rm[7], r22 = Rm[8];
    float t0 = Tv[0], t1 = Tv[1], t2 = Tv[2];

    const float INV_DFX = 1.0f / D_FX;
    const float INV_DFY = 1.0f / D_FY;

    // gy depends only on v: hoist
    float gy = __fmul_rn(__fmul_rn(__fsub_rn((float)v, D_CY), INV_DFY), SCALE_F);

    int  px0a[4], py0a[4], vba[4];
    bool maska[4], xloa[4], y1oka[4];

    #pragma unroll
    for (int j = 0; j < 4; j++) {
        int u = u0 + j;
        float dval = dvals[j];

        float gx = __fmul_rn(__fmul_rn(__fsub_rn((float)u, D_CX), INV_DFX), SCALE_F);
        float gz = SCALE_F;

        float p0 = __fmul_rn(dval, gx);
        float p1 = __fmul_rn(dval, gy);
        float p2 = __fmul_rn(dval, gz);

        // pts @ R : multiply-reduce, separate rn ops, left-assoc, NO fma.
        float x = __fadd_rn(__fadd_rn(__fmul_rn(p0, r00), __fmul_rn(p1, r10)),
                            __fmul_rn(p2, r20));
        float y = __fadd_rn(__fadd_rn(__fmul_rn(p0, r01), __fmul_rn(p1, r11)),
                            __fmul_rn(p2, r21));
        float d = __fadd_rn(__fadd_rn(__fmul_rn(p0, r02), __fmul_rn(p1, r12)),
                            __fmul_rn(p2, r22));

        x = __fadd_rn(x, t0);
        y = __fadd_rn(y, t1);
        d = __fadd_rn(d, t2);

        float dsafe = (d == 0.0f) ? 1.0f : d;
        float px = __fadd_rn(__fmul_rn(__fdiv_rn(x, dsafe), R_FX), R_CX);
        float py = __fadd_rn(__fmul_rn(__fdiv_rn(y, dsafe), R_FY), R_CY);
        if (d == 0.0f) { px = 0.0f; py = 0.0f; }

        bool mask = (px < 0.0f) | (px >= (float)IMG_W) |
                    (py < 0.0f) | (py >= (float)IMG_H);
        maska[j] = mask;
        if (mask) { px = 0.0f; py = 0.0f; }

        // trunc-toward-zero casts (frozen numerics)
        px0a[j] = (int)__fsub_rn(px, 0.5f);
        py0a[j] = (int)__fsub_rn(py, 0.5f);
        xloa[j] = (px < 0.5f);           // px1 == px0 == 0 (duplicate)
        bool ylo = (py < 0.5f);
        y1oka[j] = (!ylo) & ((py0a[j] + 1) < IMG_H);
        vba[j]  = __float_as_int(dval);
    }

    // ---- fast path: merged 5-column strip ----
    bool fp = (!maska[0]) & (!maska[1]) & (!maska[2]) & (!maska[3]) &
              (!xloa[0]) & (!xloa[1]) & (!xloa[2]) & (!xloa[3]) &
              (py0a[1] == py0a[0]) & (py0a[2] == py0a[0]) & (py0a[3] == py0a[0]) &
              (y1oka[1] == y1oka[0]) & (y1oka[2] == y1oka[0]) & (y1oka[3] == y1oka[0]) &
              (px0a[1] == px0a[0] + 1) & (px0a[2] == px0a[0] + 2) &
              (px0a[3] == px0a[0] + 3) & ((px0a[0] + 4) < IMG_W);

    if (fp) {
        int c0 = vba[0];
        int c1 = min(vba[0], vba[1]);
        int c2 = min(vba[1], vba[2]);
        int c3 = min(vba[2], vba[3]);
        int c4 = vba[3];
        int base = py0a[0] * IMG_W + px0a[0];
        atomicMin(&outbits[base + 0], c0);
        atomicMin(&outbits[base + 1], c1);
        atomicMin(&outbits[base + 2], c2);
        atomicMin(&outbits[base + 3], c3);
        atomicMin(&outbits[base + 4], c4);
        if (y1oka[0]) {
            int b2 = base + IMG_W;
            atomicMin(&outbits[b2 + 0], c0);
            atomicMin(&outbits[b2 + 1], c1);
            atomicMin(&outbits[b2 + 2], c2);
            atomicMin(&outbits[b2 + 3], c3);
            atomicMin(&outbits[b2 + 4], c4);
        }
        return;
    }

    // ---- general path: per-pixel ----
    #pragma unroll
    for (int j = 0; j < 4; j++) {
        int vb = vba[j];
        if (maska[j]) {
            // all four targets collapse to (0,0): guarded single atomic
            if (__ldcg(&outbits[0]) > vb) atomicMin(&outbits[0], vb);
            continue;
        }
        int px0 = px0a[j];
        int py0 = py0a[j];
        bool x1ok = (!xloa[j]) & ((px0 + 1) < IMG_W);
        bool y1ok = y1oka[j];

        int o00 = py0 * IMG_W + px0;
        atomicMin(&outbits[o00], vb);
        if (x1ok) atomicMin(&outbits[o00 + 1], vb);
        if (y1ok) {
            int o10 = o00 + IMG_W;
            atomicMin(&outbits[o10], vb);
            if (x1ok) atomicMin(&outbits[o10 + 1], vb);
        }
    }
}

// ---------------------------------------------------------------------------
// Kernel 3: FILL -> 0 (1x float4 per thread -- R5 shape)
// ---------------------------------------------------------------------------
__global__ void finalize_kernel(float4* __restrict__ out4) {
    int i = blockIdx.x * blockDim.x + threadIdx.x;
    if (i < NPIX / 4) {
        float4 q = out4[i];
        q.x = (q.x == FILL) ? 0.0f : q.x;
        q.y = (q.y == FILL) ? 0.0f : q.y;
        q.z = (q.z == FILL) ? 0.0f : q.z;
        q.w = (q.w == FILL) ? 0.0f : q.w;
        out4[i] = q;
    }
}

extern "C" void kernel_launch(void* const* d_in, const int* in_sizes, int n_in,
                              void* d_out, int out_size) {
    const float* depth = (const float*)d_in[0];   // [H, W, 1] float32
    const float* Rm    = (const float*)d_in[1];   // [3, 3]
    const float* Tv    = (const float*)d_in[2];   // [3]
    float* out = (float*)d_out;                   // [H, W, 1] float32

    (void)in_sizes; (void)n_in; (void)out_size;

    int threads = 256;
    int blocks4 = (NPIX / 4 + threads - 1) / threads;

    init_fill_kernel<<<blocks4, threads>>>((float4*)out);
    splat_kernel<<<blocks4, threads>>>((const float4*)depth, Rm, Tv, (int*)out);
    finalize_kernel<<<blocks4, threads>>>((float4*)out);
}